// round 15
// baseline (speedup 1.0000x reference)
#include <cuda_runtime.h>
#include <cuda_fp16.h>
#include <math.h>
#include <stdint.h>

#define NF 256
#define NH 128
#define NC 10
#define NMAX 50000
#define EMAX 800000
#define SCANB 1024
#define KC 16
#define AST 24

// Scratch
__device__ __align__(16) __half g_h[(size_t)NMAX * NH];   // fp16 GEMM output
__device__ float g_agg[(size_t)NMAX * NH];
__device__ float g_deg[NMAX];
__device__ float g_dinv[NMAX];
__device__ float g_selfc[NMAX];
__device__ int   g_cnt[NMAX];
__device__ int   g_pos[NMAX];
__device__ int   g_rowoff[NMAX + 1];
__device__ int   g_csr_src[EMAX];
__device__ float g_csr_coef[EMAX];
__device__ int   g_bsum[(NMAX + SCANB - 1) / SCANB];
// pre-converted weights (hi/lo bf16, n-major): W1 @0 (128x256), W2 @32768, W3 @49152
__device__ __align__(16) uint16_t g_whi[65536];
__device__ __align__(16) uint16_t g_wlo[65536];

// ---------------- helpers ------------------------------------------------
__device__ __forceinline__ uint32_t smem_u32(const void* p) {
    uint32_t a;
    asm("{ .reg .u64 t; cvta.to.shared.u64 t, %1; cvt.u32.u64 %0, t; }"
        : "=r"(a) : "l"(p));
    return a;
}
__device__ __forceinline__ uint32_t pack_bf(float a, float b) {
    uint32_t r;
    asm("cvt.rn.bf16x2.f32 %0, %1, %2;" : "=r"(r) : "f"(b), "f"(a));
    return r;
}
__device__ __forceinline__ float bflo_f(uint32_t p) { return __uint_as_float(p << 16); }
__device__ __forceinline__ float bfhi_f(uint32_t p) { return __uint_as_float(p & 0xffff0000u); }

__device__ __forceinline__ void ldm4(uint32_t* r, uint32_t addr) {
    asm volatile("ldmatrix.sync.aligned.m8n8.x4.shared.b16 {%0,%1,%2,%3}, [%4];"
                 : "=r"(r[0]), "=r"(r[1]), "=r"(r[2]), "=r"(r[3]) : "r"(addr));
}
__device__ __forceinline__ void ldm2(uint32_t* r, uint32_t addr) {
    asm volatile("ldmatrix.sync.aligned.m8n8.x2.shared.b16 {%0,%1}, [%2];"
                 : "=r"(r[0]), "=r"(r[1]) : "r"(addr));
}
__device__ __forceinline__ void mma_bf16(float* d, const uint32_t* a, const uint32_t* b) {
    asm volatile(
        "mma.sync.aligned.m16n8k16.row.col.f32.bf16.bf16.f32 "
        "{%0,%1,%2,%3}, {%4,%5,%6,%7}, {%8,%9}, {%0,%1,%2,%3};"
        : "+f"(d[0]), "+f"(d[1]), "+f"(d[2]), "+f"(d[3])
        : "r"(a[0]), "r"(a[1]), "r"(a[2]), "r"(a[3]), "r"(b[0]), "r"(b[1]));
}

// ---------------- W pre-conversion (all 3 layers, one launch) -------------
__global__ void prep_w(const float* __restrict__ W1, const float* __restrict__ W2,
                       const float* __restrict__ W3) {
    int idx = blockIdx.x * blockDim.x + threadIdx.x;   // 0..65535
    const float* W;
    int n, k, K, off;
    if (idx < 32768) {
        W = W1; K = 256; off = 0;
        n = idx >> 8; k = idx & 255;
    } else if (idx < 49152) {
        int i2 = idx - 32768;
        W = W2; K = 128; off = 32768;
        n = i2 >> 7; k = i2 & 127;
    } else {
        int i2 = idx - 49152;
        W = W3; K = 128; off = 49152;
        n = i2 >> 7; k = i2 & 127;
    }
    float v = W[(size_t)k * 128 + n];
    uint32_t hp = pack_bf(v, v);
    float lo = v - bflo_f(hp);
    uint32_t lp = pack_bf(lo, lo);
    g_whi[off + n * K + k] = (uint16_t)hp;
    g_wlo[off + n * K + k] = (uint16_t)lp;
}

// ======================= tensor-core GEMM (mma.sync, bf16 split) =========
// Cm[N x 128] (fp16) = A[N x K] (fp32) @ W (pre-converted hi/lo, n-major)
// KC=16, 128-row tiles, 256 threads, 2 CTAs/SM (r13 config + copy-fill B).
__global__ __launch_bounds__(256, 2) void tc_gemm(const float* __restrict__ A,
                                                  const uint16_t* __restrict__ Whi,
                                                  const uint16_t* __restrict__ Wlo,
                                                  __half* __restrict__ Cm,
                                                  int N, int K, int reluA) {
    __shared__ __align__(16) uint16_t Ah[128 * AST];
    __shared__ __align__(16) uint16_t Al[128 * AST];
    __shared__ __align__(16) uint16_t Bh[128 * AST];
    __shared__ __align__(16) uint16_t Bl[128 * AST];

    int tid = threadIdx.x;
    int lane = tid & 31;
    int wid = tid >> 5;
    int wm = wid & 1;
    int wn = wid >> 1;
    int row0 = blockIdx.x * 128;

    float acc[4][4][4];
#pragma unroll
    for (int i = 0; i < 4; i++)
#pragma unroll
        for (int j = 0; j < 4; j++)
#pragma unroll
            for (int q = 0; q < 4; q++) acc[i][j][q] = 0.f;

    uint32_t aBase = smem_u32(Ah);
    uint32_t alBase = smem_u32(Al);
    uint32_t bBase = smem_u32(Bh);
    uint32_t blBase = smem_u32(Bl);

    int aLRow = lane & 15;
    int aLK = (lane >> 4) * 8;
    int bLRow = lane & 7;
    int bLK = ((lane >> 3) & 1) * 8;

    // B-fill decomposition: thread t -> n = t>>1, half = t&1 (8 k-values = uint4)
    int bN = tid >> 1;
    int bHalf = (tid & 1) * 8;

    for (int kb = 0; kb < K; kb += KC) {
        // ---- fill A: 128 rows x 16 k (fp32 -> hi/lo bf16) ----
#pragma unroll
        for (int it = 0; it < 2; it++) {
            int idx = tid + it * 256;      // 0..511
            int row = idx >> 2;
            int f4 = idx & 3;
            float4 v = make_float4(0.f, 0.f, 0.f, 0.f);
            int gr = row0 + row;
            if (gr < N)
                v = *reinterpret_cast<const float4*>(A + (size_t)gr * K + kb + f4 * 4);
            if (reluA) {
                v.x = fmaxf(v.x, 0.f); v.y = fmaxf(v.y, 0.f);
                v.z = fmaxf(v.z, 0.f); v.w = fmaxf(v.w, 0.f);
            }
            uint32_t h01 = pack_bf(v.x, v.y);
            uint32_t h23 = pack_bf(v.z, v.w);
            uint32_t l01 = pack_bf(v.x - bflo_f(h01), v.y - bfhi_f(h01));
            uint32_t l23 = pack_bf(v.z - bflo_f(h23), v.w - bfhi_f(h23));
            int o = row * AST + f4 * 4;
            *reinterpret_cast<uint2*>(Ah + o) = make_uint2(h01, h23);
            *reinterpret_cast<uint2*>(Al + o) = make_uint2(l01, l23);
        }
        // ---- fill B: straight copy of pre-converted rows ----
        {
            uint4 h = *reinterpret_cast<const uint4*>(Whi + (size_t)bN * K + kb + bHalf);
            uint4 l = *reinterpret_cast<const uint4*>(Wlo + (size_t)bN * K + kb + bHalf);
            *reinterpret_cast<uint4*>(Bh + bN * AST + bHalf) = h;
            *reinterpret_cast<uint4*>(Bl + bN * AST + bHalf) = l;
        }
        __syncthreads();

        // ---- mma: single k16 step per chunk ----
        {
            uint32_t afh[4][4], afl[4][4];
#pragma unroll
            for (int mt = 0; mt < 4; mt++) {
                uint32_t off = (uint32_t)(((wm * 64 + mt * 16 + aLRow) * AST +
                                           aLK) * 2);
                ldm4(afh[mt], aBase + off);
                ldm4(afl[mt], alBase + off);
            }
            uint32_t bfh[4][2], bfl[4][2];
#pragma unroll
            for (int nt = 0; nt < 4; nt++) {
                uint32_t off = (uint32_t)(((wn * 32 + nt * 8 + bLRow) * AST +
                                           bLK) * 2);
                ldm2(bfh[nt], bBase + off);
                ldm2(bfl[nt], blBase + off);
            }
#pragma unroll
            for (int mt = 0; mt < 4; mt++)
#pragma unroll
                for (int nt = 0; nt < 4; nt++) {
                    mma_bf16(acc[mt][nt], afh[mt], bfh[nt]);
                    mma_bf16(acc[mt][nt], afh[mt], bfl[nt]);
                    mma_bf16(acc[mt][nt], afl[mt], bfh[nt]);
                }
        }
        __syncthreads();
    }

    int gid = lane >> 2;
    int tig = lane & 3;
#pragma unroll
    for (int mt = 0; mt < 4; mt++) {
        int r0 = row0 + wm * 64 + mt * 16 + gid;
        int r1 = r0 + 8;
#pragma unroll
        for (int nt = 0; nt < 4; nt++) {
            int col = wn * 32 + nt * 8 + tig * 2;
            if (r0 < N) {
                __half2 p = __floats2half2_rn(acc[mt][nt][0], acc[mt][nt][1]);
                *reinterpret_cast<__half2*>(Cm + (size_t)r0 * 128 + col) = p;
            }
            if (r1 < N) {
                __half2 p = __floats2half2_rn(acc[mt][nt][2], acc[mt][nt][3]);
                *reinterpret_cast<__half2*>(Cm + (size_t)r1 * 128 + col) = p;
            }
        }
    }
}

// ---------------- precompute ---------------------------------------------
__global__ void init_deg_kernel(int n) {
    int i = blockIdx.x * blockDim.x + threadIdx.x;
    if (i < n) { g_deg[i] = 1.0f; g_cnt[i] = 0; }
}

__global__ void accum_deg_kernel(const int* __restrict__ dst,
                                 const float* __restrict__ ew, int E) {
    int e = blockIdx.x * blockDim.x + threadIdx.x;
    if (e < E) {
        int d = dst[e];
        atomicAdd(&g_deg[d], ew[e]);
        atomicAdd(&g_cnt[d], 1);
    }
}

// scan phase1 with dinv fused
__global__ __launch_bounds__(SCANB) void scan_phase1(int n) {
    __shared__ int warpsum[32];
    int tid = threadIdx.x, lane = tid & 31, wid = tid >> 5;
    int i = blockIdx.x * SCANB + tid;

    if (i < n) {
        float d = g_deg[i];
        float r = (d > 0.0f) ? rsqrtf(d) : 0.0f;
        g_dinv[i] = r;
        g_selfc[i] = r * r;
    }

    int v = (i < n) ? g_cnt[i] : 0;
    int x = v;
#pragma unroll
    for (int off = 1; off < 32; off <<= 1) {
        int y = __shfl_up_sync(0xffffffffu, x, off);
        if (lane >= off) x += y;
    }
    if (lane == 31) warpsum[wid] = x;
    __syncthreads();
    if (wid == 0) {
        int s = warpsum[lane];
#pragma unroll
        for (int off = 1; off < 32; off <<= 1) {
            int y = __shfl_up_sync(0xffffffffu, s, off);
            if (lane >= off) s += y;
        }
        warpsum[lane] = s;
    }
    __syncthreads();
    int woff = wid ? warpsum[wid - 1] : 0;
    if (i < n) g_rowoff[i] = x + woff - v;
    if (tid == SCANB - 1) g_bsum[blockIdx.x] = x + woff;
}

// scan phase2+3 merged
__global__ void scan_phase23(int nb, int n) {
    __shared__ int boff_s[64];
    __shared__ int ws2[2];
    int tid = threadIdx.x;
    int lane = tid & 31;
    int w = tid >> 5;

    int v = 0, x = 0;
    if (tid < 64) {
        v = (tid < nb) ? g_bsum[tid] : 0;
        x = v;
#pragma unroll
        for (int off = 1; off < 32; off <<= 1) {
            int y = __shfl_up_sync(0xffffffffu, x, off);
            if (lane >= off) x += y;
        }
        if (lane == 31) ws2[w] = x;
    }
    __syncthreads();
    if (tid < 64) {
        int add = (w == 1) ? ws2[0] : 0;
        boff_s[tid] = x + add - v;
        if (blockIdx.x == 0 && tid == nb - 1) g_rowoff[n] = x + add;
    }
    __syncthreads();

    int i = blockIdx.x * blockDim.x + tid;
    if (i < n) {
        int r = g_rowoff[i] + boff_s[i / SCANB];
        g_rowoff[i] = r;
        g_pos[i] = r;
    }
}

__global__ void fill_kernel(const int* __restrict__ src, const int* __restrict__ dst,
                            const float* __restrict__ ew, int E) {
    int e = blockIdx.x * blockDim.x + threadIdx.x;
    if (e < E) {
        int s = src[e], d = dst[e];
        int slot = atomicAdd(&g_pos[d], 1);
        g_csr_src[slot] = s;
        g_csr_coef[slot] = g_dinv[s] * ew[e] * g_dinv[d];
    }
}

// ---------------- CSR gather aggregation (warp per node, fp16 h) ---------
__global__ void gather_kernel(const float* __restrict__ b, int n) {
    int t = blockIdx.x * blockDim.x + threadIdx.x;
    int node = t >> 5;
    int lane = t & 31;
    if (node >= n) return;

    const __half2* h2 = reinterpret_cast<const __half2*>(g_h);
    float4 bv = reinterpret_cast<const float4*>(b)[lane];
    float sc = g_selfc[node];

    float4 acc;
    {
        __half2 a0 = h2[(size_t)node * 64 + 2 * lane];
        __half2 a1 = h2[(size_t)node * 64 + 2 * lane + 1];
        float2 f0 = __half22float2(a0);
        float2 f1 = __half22float2(a1);
        acc.x = fmaf(f0.x, sc, bv.x);
        acc.y = fmaf(f0.y, sc, bv.y);
        acc.z = fmaf(f1.x, sc, bv.z);
        acc.w = fmaf(f1.y, sc, bv.w);
    }

    int beg = g_rowoff[node];
    int end = g_rowoff[node + 1];
    int e = beg;
    for (; e + 3 < end; e += 4) {
        int s0 = __ldg(g_csr_src + e);
        int s1 = __ldg(g_csr_src + e + 1);
        int s2 = __ldg(g_csr_src + e + 2);
        int s3 = __ldg(g_csr_src + e + 3);
        float w0 = __ldg(g_csr_coef + e);
        float w1 = __ldg(g_csr_coef + e + 1);
        float w2 = __ldg(g_csr_coef + e + 2);
        float w3 = __ldg(g_csr_coef + e + 3);
        __half2 a0 = h2[(size_t)s0 * 64 + 2 * lane];
        __half2 a1 = h2[(size_t)s0 * 64 + 2 * lane + 1];
        __half2 c0 = h2[(size_t)s1 * 64 + 2 * lane];
        __half2 c1 = h2[(size_t)s1 * 64 + 2 * lane + 1];
        __half2 d0 = h2[(size_t)s2 * 64 + 2 * lane];
        __half2 d1 = h2[(size_t)s2 * 64 + 2 * lane + 1];
        __half2 e0 = h2[(size_t)s3 * 64 + 2 * lane];
        __half2 e1 = h2[(size_t)s3 * 64 + 2 * lane + 1];
        float2 f0 = __half22float2(a0);
        float2 f1 = __half22float2(a1);
        float2 g0 = __half22float2(c0);
        float2 g1 = __half22float2(c1);
        float2 h0 = __half22float2(d0);
        float2 h1 = __half22float2(d1);
        float2 i0 = __half22float2(e0);
        float2 i1 = __half22float2(e1);
        acc.x = fmaf(f0.x, w0, acc.x);
        acc.y = fmaf(f0.y, w0, acc.y);
        acc.z = fmaf(f1.x, w0, acc.z);
        acc.w = fmaf(f1.y, w0, acc.w);
        acc.x = fmaf(g0.x, w1, acc.x);
        acc.y = fmaf(g0.y, w1, acc.y);
        acc.z = fmaf(g1.x, w1, acc.z);
        acc.w = fmaf(g1.y, w1, acc.w);
        acc.x = fmaf(h0.x, w2, acc.x);
        acc.y = fmaf(h0.y, w2, acc.y);
        acc.z = fmaf(h1.x, w2, acc.z);
        acc.w = fmaf(h1.y, w2, acc.w);
        acc.x = fmaf(i0.x, w3, acc.x);
        acc.y = fmaf(i0.y, w3, acc.y);
        acc.z = fmaf(i1.x, w3, acc.z);
        acc.w = fmaf(i1.y, w3, acc.w);
    }
    for (; e < end; e++) {
        int s0 = __ldg(g_csr_src + e);
        float w0 = __ldg(g_csr_coef + e);
        __half2 a0 = h2[(size_t)s0 * 64 + 2 * lane];
        __half2 a1 = h2[(size_t)s0 * 64 + 2 * lane + 1];
        float2 f0 = __half22float2(a0);
        float2 f1 = __half22float2(a1);
        acc.x = fmaf(f0.x, w0, acc.x);
        acc.y = fmaf(f0.y, w0, acc.y);
        acc.z = fmaf(f1.x, w0, acc.z);
        acc.w = fmaf(f1.y, w0, acc.w);
    }
    reinterpret_cast<float4*>(g_agg)[(size_t)node * 32 + lane] = acc;
}

// ---------------- FC + softmax (warp per node) ---------------------------
__global__ void fc_softmax_kernel(const float* __restrict__ fw,
                                  const float* __restrict__ fb,
                                  float* __restrict__ out, int n) {
    int warp = (blockIdx.x * blockDim.x + threadIdx.x) >> 5;
    int lane = threadIdx.x & 31;
    if (warp >= n) return;
    const float* hr = g_agg + (size_t)warp * NH;

    float acc[NC];
#pragma unroll
    for (int c = 0; c < NC; c++) acc[c] = 0.0f;
#pragma unroll
    for (int kk = 0; kk < 4; kk++) {
        int k = lane + kk * 32;
        float hv = fmaxf(hr[k], 0.0f);
#pragma unroll
        for (int c = 0; c < NC; c++) acc[c] = fmaf(hv, __ldg(fw + k * NC + c), acc[c]);
    }
#pragma unroll
    for (int c = 0; c < NC; c++) {
#pragma unroll
        for (int off = 16; off; off >>= 1)
            acc[c] += __shfl_xor_sync(0xffffffffu, acc[c], off);
        acc[c] += fb[c];
    }
    float mx = acc[0];
#pragma unroll
    for (int c = 1; c < NC; c++) mx = fmaxf(mx, acc[c]);
    float ex[NC];
    float sum = 0.0f;
#pragma unroll
    for (int c = 0; c < NC; c++) { ex[c] = __expf(acc[c] - mx); sum += ex[c]; }
    float inv = 1.0f / sum;
    if (lane < NC) out[(size_t)warp * NC + lane] = ex[lane] * inv;
}

// ---------------- launch -------------------------------------------------
extern "C" void kernel_launch(void* const* d_in, const int* in_sizes, int n_in,
                              void* d_out, int out_size) {
    const float* x  = (const float*)d_in[0];
    const int*   ei = (const int*)d_in[1];
    const float* ew = (const float*)d_in[2];
    const float* W1 = (const float*)d_in[3];
    const float* b1 = (const float*)d_in[4];
    const float* W2 = (const float*)d_in[5];
    const float* b2 = (const float*)d_in[6];
    const float* W3 = (const float*)d_in[7];
    const float* b3 = (const float*)d_in[8];
    const float* fw = (const float*)d_in[9];
    const float* fb = (const float*)d_in[10];
    float* out = (float*)d_out;

    int N = in_sizes[0] / NF;
    int E = in_sizes[2];
    const int* src = ei;
    const int* dst = ei + E;

    __half* hbuf;
    float* aggbuf;
    uint16_t *whi, *wlo;
    cudaGetSymbolAddress((void**)&hbuf, g_h);
    cudaGetSymbolAddress((void**)&aggbuf, g_agg);
    cudaGetSymbolAddress((void**)&whi, g_whi);
    cudaGetSymbolAddress((void**)&wlo, g_wlo);

    const int T = 256;
    int gN = (N + T - 1) / T;
    int gE = (E + T - 1) / T;
    int gGa = (N * 32 + T - 1) / T;
    int gG = (N + 127) / 128;
    int nb = (N + SCANB - 1) / SCANB;

    prep_w<<<256, 256>>>(W1, W2, W3);
    init_deg_kernel<<<gN, T>>>(N);
    accum_deg_kernel<<<gE, T>>>(dst, ew, E);
    scan_phase1<<<nb, SCANB>>>(N);
    scan_phase23<<<gN, T>>>(nb, N);
    fill_kernel<<<gE, T>>>(src, dst, ew, E);

    tc_gemm<<<gG, T>>>(x, whi, wlo, hbuf, N, NF, 0);
    gather_kernel<<<gGa, T>>>(b1, N);
    tc_gemm<<<gG, T>>>(aggbuf, whi + 32768, wlo + 32768, hbuf, N, NH, 1);
    gather_kernel<<<gGa, T>>>(b2, N);
    tc_gemm<<<gG, T>>>(aggbuf, whi + 49152, wlo + 49152, hbuf, N, NH, 1);
    gather_kernel<<<gGa, T>>>(b3, N);
    fc_softmax_kernel<<<gGa, T>>>(fw, fb, out, N);
}

// round 16
// speedup vs baseline: 1.1399x; 1.1399x over previous
#include <cuda_runtime.h>
#include <cuda_fp16.h>
#include <math.h>
#include <stdint.h>

#define NF 256
#define NH 128
#define NC 10
#define NMAX 50000
#define EMAX 800000
#define SCANB 1024
#define KC 16
#define AST 24

// Scratch
__device__ __align__(16) __half g_h[(size_t)NMAX * NH];   // fp16 GEMM output
__device__ float g_agg[(size_t)NMAX * NH];
__device__ float g_deg[NMAX];
__device__ float g_dinv[NMAX];
__device__ float g_selfc[NMAX];
__device__ int   g_cnt[NMAX];
__device__ int   g_pos[NMAX];
__device__ int   g_rowoff[NMAX + 1];
__device__ int   g_csr_src[EMAX];
__device__ float g_csr_coef[EMAX];
__device__ int   g_bsum[(NMAX + SCANB - 1) / SCANB];
// pre-converted W, k2-major packed bf16x2 (lo=W[2k2][n], hi=W[2k2+1][n]):
// W1 @0 (128 k2 x 128 n), W2 @16384 (64x128), W3 @24576 (64x128)
__device__ __align__(16) uint32_t g_whp[32768];
__device__ __align__(16) uint32_t g_wlp[32768];

// ---------------- helpers ------------------------------------------------
__device__ __forceinline__ uint32_t smem_u32(const void* p) {
    uint32_t a;
    asm("{ .reg .u64 t; cvta.to.shared.u64 t, %1; cvt.u32.u64 %0, t; }"
        : "=r"(a) : "l"(p));
    return a;
}
__device__ __forceinline__ uint32_t pack_bf(float a, float b) {
    uint32_t r;
    asm("cvt.rn.bf16x2.f32 %0, %1, %2;" : "=r"(r) : "f"(b), "f"(a));
    return r;
}
__device__ __forceinline__ float bflo_f(uint32_t p) { return __uint_as_float(p << 16); }
__device__ __forceinline__ float bfhi_f(uint32_t p) { return __uint_as_float(p & 0xffff0000u); }

__device__ __forceinline__ void ldm4(uint32_t* r, uint32_t addr) {
    asm volatile("ldmatrix.sync.aligned.m8n8.x4.shared.b16 {%0,%1,%2,%3}, [%4];"
                 : "=r"(r[0]), "=r"(r[1]), "=r"(r[2]), "=r"(r[3]) : "r"(addr));
}
__device__ __forceinline__ void ldm2(uint32_t* r, uint32_t addr) {
    asm volatile("ldmatrix.sync.aligned.m8n8.x2.shared.b16 {%0,%1}, [%2];"
                 : "=r"(r[0]), "=r"(r[1]) : "r"(addr));
}
__device__ __forceinline__ void mma_bf16(float* d, const uint32_t* a, const uint32_t* b) {
    asm volatile(
        "mma.sync.aligned.m16n8k16.row.col.f32.bf16.bf16.f32 "
        "{%0,%1,%2,%3}, {%4,%5,%6,%7}, {%8,%9}, {%0,%1,%2,%3};"
        : "+f"(d[0]), "+f"(d[1]), "+f"(d[2]), "+f"(d[3])
        : "r"(a[0]), "r"(a[1]), "r"(a[2]), "r"(a[3]), "r"(b[0]), "r"(b[1]));
}

// ---------------- W pre-conversion (k2-major packed, coalesced) ----------
__global__ void prep_w(const float* __restrict__ W1, const float* __restrict__ W2,
                       const float* __restrict__ W3) {
    int idx = blockIdx.x * blockDim.x + threadIdx.x;   // 0..32767
    const float* W;
    int k2, n, off;
    if (idx < 16384) {
        W = W1; off = 0;
        k2 = idx >> 7; n = idx & 127;
    } else if (idx < 24576) {
        int i2 = idx - 16384;
        W = W2; off = 16384;
        k2 = i2 >> 7; n = i2 & 127;
    } else {
        int i2 = idx - 24576;
        W = W3; off = 24576;
        k2 = i2 >> 7; n = i2 & 127;
    }
    float v0 = W[(size_t)(2 * k2) * 128 + n];
    float v1 = W[(size_t)(2 * k2 + 1) * 128 + n];
    uint32_t h = pack_bf(v0, v1);
    uint32_t l = pack_bf(v0 - bflo_f(h), v1 - bfhi_f(h));
    g_whp[off + idx - off] = h;   // == g_whp[idx]
    g_wlp[idx] = l;
}

// ======================= tensor-core GEMM (mma.sync, bf16 split) =========
// r13 config: KC=16, 128-row tiles, 256 threads, 2 CTAs/SM.
// B-fill: coalesced uint32 copy from k2-major packed pre-converted W.
__global__ __launch_bounds__(256, 2) void tc_gemm(const float* __restrict__ A,
                                                  const uint32_t* __restrict__ Whp,
                                                  const uint32_t* __restrict__ Wlp,
                                                  __half* __restrict__ Cm,
                                                  int N, int K, int reluA) {
    __shared__ __align__(16) uint16_t Ah[128 * AST];
    __shared__ __align__(16) uint16_t Al[128 * AST];
    __shared__ __align__(16) uint16_t Bh[128 * AST];
    __shared__ __align__(16) uint16_t Bl[128 * AST];

    int tid = threadIdx.x;
    int lane = tid & 31;
    int wid = tid >> 5;
    int wm = wid & 1;
    int wn = wid >> 1;
    int row0 = blockIdx.x * 128;

    float acc[4][4][4];
#pragma unroll
    for (int i = 0; i < 4; i++)
#pragma unroll
        for (int j = 0; j < 4; j++)
#pragma unroll
            for (int q = 0; q < 4; q++) acc[i][j][q] = 0.f;

    uint32_t aBase = smem_u32(Ah);
    uint32_t alBase = smem_u32(Al);
    uint32_t bBase = smem_u32(Bh);
    uint32_t blBase = smem_u32(Bl);

    int aLRow = lane & 15;
    int aLK = (lane >> 4) * 8;
    int bLRow = lane & 7;
    int bLK = ((lane >> 3) & 1) * 8;

    for (int kb = 0; kb < K; kb += KC) {
        // ---- fill A: 128 rows x 16 k (fp32 -> hi/lo bf16) ----
#pragma unroll
        for (int it = 0; it < 2; it++) {
            int idx = tid + it * 256;      // 0..511
            int row = idx >> 2;
            int f4 = idx & 3;
            float4 v = make_float4(0.f, 0.f, 0.f, 0.f);
            int gr = row0 + row;
            if (gr < N)
                v = *reinterpret_cast<const float4*>(A + (size_t)gr * K + kb + f4 * 4);
            if (reluA) {
                v.x = fmaxf(v.x, 0.f); v.y = fmaxf(v.y, 0.f);
                v.z = fmaxf(v.z, 0.f); v.w = fmaxf(v.w, 0.f);
            }
            uint32_t h01 = pack_bf(v.x, v.y);
            uint32_t h23 = pack_bf(v.z, v.w);
            uint32_t l01 = pack_bf(v.x - bflo_f(h01), v.y - bfhi_f(h01));
            uint32_t l23 = pack_bf(v.z - bflo_f(h23), v.w - bfhi_f(h23));
            int o = row * AST + f4 * 4;
            *reinterpret_cast<uint2*>(Ah + o) = make_uint2(h01, h23);
            *reinterpret_cast<uint2*>(Al + o) = make_uint2(l01, l23);
        }
        // ---- fill B: coalesced packed copy (8 k2 x 128 n per chunk) ----
        {
            int kb2 = kb >> 1;             // packed k2 base
#pragma unroll
            for (int it = 0; it < 4; it++) {
                int idx = tid + it * 256;  // 0..1023
                int k2 = idx >> 7;         // 0..7
                int n = idx & 127;
                uint32_t h = __ldg(Whp + (size_t)(kb2 + k2) * 128 + n);
                uint32_t l = __ldg(Wlp + (size_t)(kb2 + k2) * 128 + n);
                int o = n * AST + k2 * 2;
                *reinterpret_cast<uint32_t*>(Bh + o) = h;
                *reinterpret_cast<uint32_t*>(Bl + o) = l;
            }
        }
        __syncthreads();

        // ---- mma: single k16 step per chunk ----
        {
            uint32_t afh[4][4], afl[4][4];
#pragma unroll
            for (int mt = 0; mt < 4; mt++) {
                uint32_t off = (uint32_t)(((wm * 64 + mt * 16 + aLRow) * AST +
                                           aLK) * 2);
                ldm4(afh[mt], aBase + off);
                ldm4(afl[mt], alBase + off);
            }
            uint32_t bfh[4][2], bfl[4][2];
#pragma unroll
            for (int nt = 0; nt < 4; nt++) {
                uint32_t off = (uint32_t)(((wn * 32 + nt * 8 + bLRow) * AST +
                                           bLK) * 2);
                ldm2(bfh[nt], bBase + off);
                ldm2(bfl[nt], blBase + off);
            }
#pragma unroll
            for (int mt = 0; mt < 4; mt++)
#pragma unroll
                for (int nt = 0; nt < 4; nt++) {
                    mma_bf16(acc[mt][nt], afh[mt], bfh[nt]);
                    mma_bf16(acc[mt][nt], afh[mt], bfl[nt]);
                    mma_bf16(acc[mt][nt], afl[mt], bfh[nt]);
                }
        }
        __syncthreads();
    }

    int gid = lane >> 2;
    int tig = lane & 3;
#pragma unroll
    for (int mt = 0; mt < 4; mt++) {
        int r0 = row0 + wm * 64 + mt * 16 + gid;
        int r1 = r0 + 8;
#pragma unroll
        for (int nt = 0; nt < 4; nt++) {
            int col = wn * 32 + nt * 8 + tig * 2;
            if (r0 < N) {
                __half2 p = __floats2half2_rn(acc[mt][nt][0], acc[mt][nt][1]);
                *reinterpret_cast<__half2*>(Cm + (size_t)r0 * 128 + col) = p;
            }
            if (r1 < N) {
                __half2 p = __floats2half2_rn(acc[mt][nt][2], acc[mt][nt][3]);
                *reinterpret_cast<__half2*>(Cm + (size_t)r1 * 128 + col) = p;
            }
        }
    }
}

// ---------------- precompute ---------------------------------------------
__global__ void init_deg_kernel(int n) {
    int i = blockIdx.x * blockDim.x + threadIdx.x;
    if (i < n) { g_deg[i] = 1.0f; g_cnt[i] = 0; }
}

__global__ void accum_deg_kernel(const int* __restrict__ dst,
                                 const float* __restrict__ ew, int E) {
    int e = blockIdx.x * blockDim.x + threadIdx.x;
    if (e < E) {
        int d = dst[e];
        atomicAdd(&g_deg[d], ew[e]);
        atomicAdd(&g_cnt[d], 1);
    }
}

// scan phase1 with dinv fused
__global__ __launch_bounds__(SCANB) void scan_phase1(int n) {
    __shared__ int warpsum[32];
    int tid = threadIdx.x, lane = tid & 31, wid = tid >> 5;
    int i = blockIdx.x * SCANB + tid;

    if (i < n) {
        float d = g_deg[i];
        float r = (d > 0.0f) ? rsqrtf(d) : 0.0f;
        g_dinv[i] = r;
        g_selfc[i] = r * r;
    }

    int v = (i < n) ? g_cnt[i] : 0;
    int x = v;
#pragma unroll
    for (int off = 1; off < 32; off <<= 1) {
        int y = __shfl_up_sync(0xffffffffu, x, off);
        if (lane >= off) x += y;
    }
    if (lane == 31) warpsum[wid] = x;
    __syncthreads();
    if (wid == 0) {
        int s = warpsum[lane];
#pragma unroll
        for (int off = 1; off < 32; off <<= 1) {
            int y = __shfl_up_sync(0xffffffffu, s, off);
            if (lane >= off) s += y;
        }
        warpsum[lane] = s;
    }
    __syncthreads();
    int woff = wid ? warpsum[wid - 1] : 0;
    if (i < n) g_rowoff[i] = x + woff - v;
    if (tid == SCANB - 1) g_bsum[blockIdx.x] = x + woff;
}

// scan phase2+3 merged
__global__ void scan_phase23(int nb, int n) {
    __shared__ int boff_s[64];
    __shared__ int ws2[2];
    int tid = threadIdx.x;
    int lane = tid & 31;
    int w = tid >> 5;

    int v = 0, x = 0;
    if (tid < 64) {
        v = (tid < nb) ? g_bsum[tid] : 0;
        x = v;
#pragma unroll
        for (int off = 1; off < 32; off <<= 1) {
            int y = __shfl_up_sync(0xffffffffu, x, off);
            if (lane >= off) x += y;
        }
        if (lane == 31) ws2[w] = x;
    }
    __syncthreads();
    if (tid < 64) {
        int add = (w == 1) ? ws2[0] : 0;
        boff_s[tid] = x + add - v;
        if (blockIdx.x == 0 && tid == nb - 1) g_rowoff[n] = x + add;
    }
    __syncthreads();

    int i = blockIdx.x * blockDim.x + tid;
    if (i < n) {
        int r = g_rowoff[i] + boff_s[i / SCANB];
        g_rowoff[i] = r;
        g_pos[i] = r;
    }
}

__global__ void fill_kernel(const int* __restrict__ src, const int* __restrict__ dst,
                            const float* __restrict__ ew, int E) {
    int e = blockIdx.x * blockDim.x + threadIdx.x;
    if (e < E) {
        int s = src[e], d = dst[e];
        int slot = atomicAdd(&g_pos[d], 1);
        g_csr_src[slot] = s;
        g_csr_coef[slot] = g_dinv[s] * ew[e] * g_dinv[d];
    }
}

// ---------------- CSR gather aggregation (warp per node, fp16 h) ---------
__global__ void gather_kernel(const float* __restrict__ b, int n) {
    int t = blockIdx.x * blockDim.x + threadIdx.x;
    int node = t >> 5;
    int lane = t & 31;
    if (node >= n) return;

    const __half2* h2 = reinterpret_cast<const __half2*>(g_h);
    float4 bv = reinterpret_cast<const float4*>(b)[lane];
    float sc = g_selfc[node];

    float4 acc;
    {
        __half2 a0 = h2[(size_t)node * 64 + 2 * lane];
        __half2 a1 = h2[(size_t)node * 64 + 2 * lane + 1];
        float2 f0 = __half22float2(a0);
        float2 f1 = __half22float2(a1);
        acc.x = fmaf(f0.x, sc, bv.x);
        acc.y = fmaf(f0.y, sc, bv.y);
        acc.z = fmaf(f1.x, sc, bv.z);
        acc.w = fmaf(f1.y, sc, bv.w);
    }

    int beg = g_rowoff[node];
    int end = g_rowoff[node + 1];
    int e = beg;
    for (; e + 3 < end; e += 4) {
        int s0 = __ldg(g_csr_src + e);
        int s1 = __ldg(g_csr_src + e + 1);
        int s2 = __ldg(g_csr_src + e + 2);
        int s3 = __ldg(g_csr_src + e + 3);
        float w0 = __ldg(g_csr_coef + e);
        float w1 = __ldg(g_csr_coef + e + 1);
        float w2 = __ldg(g_csr_coef + e + 2);
        float w3 = __ldg(g_csr_coef + e + 3);
        __half2 a0 = h2[(size_t)s0 * 64 + 2 * lane];
        __half2 a1 = h2[(size_t)s0 * 64 + 2 * lane + 1];
        __half2 c0 = h2[(size_t)s1 * 64 + 2 * lane];
        __half2 c1 = h2[(size_t)s1 * 64 + 2 * lane + 1];
        __half2 d0 = h2[(size_t)s2 * 64 + 2 * lane];
        __half2 d1 = h2[(size_t)s2 * 64 + 2 * lane + 1];
        __half2 e0 = h2[(size_t)s3 * 64 + 2 * lane];
        __half2 e1 = h2[(size_t)s3 * 64 + 2 * lane + 1];
        float2 f0 = __half22float2(a0);
        float2 f1 = __half22float2(a1);
        float2 g0 = __half22float2(c0);
        float2 g1 = __half22float2(c1);
        float2 h0 = __half22float2(d0);
        float2 h1 = __half22float2(d1);
        float2 i0 = __half22float2(e0);
        float2 i1 = __half22float2(e1);
        acc.x = fmaf(f0.x, w0, acc.x);
        acc.y = fmaf(f0.y, w0, acc.y);
        acc.z = fmaf(f1.x, w0, acc.z);
        acc.w = fmaf(f1.y, w0, acc.w);
        acc.x = fmaf(g0.x, w1, acc.x);
        acc.y = fmaf(g0.y, w1, acc.y);
        acc.z = fmaf(g1.x, w1, acc.z);
        acc.w = fmaf(g1.y, w1, acc.w);
        acc.x = fmaf(h0.x, w2, acc.x);
        acc.y = fmaf(h0.y, w2, acc.y);
        acc.z = fmaf(h1.x, w2, acc.z);
        acc.w = fmaf(h1.y, w2, acc.w);
        acc.x = fmaf(i0.x, w3, acc.x);
        acc.y = fmaf(i0.y, w3, acc.y);
        acc.z = fmaf(i1.x, w3, acc.z);
        acc.w = fmaf(i1.y, w3, acc.w);
    }
    for (; e < end; e++) {
        int s0 = __ldg(g_csr_src + e);
        float w0 = __ldg(g_csr_coef + e);
        __half2 a0 = h2[(size_t)s0 * 64 + 2 * lane];
        __half2 a1 = h2[(size_t)s0 * 64 + 2 * lane + 1];
        float2 f0 = __half22float2(a0);
        float2 f1 = __half22float2(a1);
        acc.x = fmaf(f0.x, w0, acc.x);
        acc.y = fmaf(f0.y, w0, acc.y);
        acc.z = fmaf(f1.x, w0, acc.z);
        acc.w = fmaf(f1.y, w0, acc.w);
    }
    reinterpret_cast<float4*>(g_agg)[(size_t)node * 32 + lane] = acc;
}

// ---------------- FC + softmax (warp per node) ---------------------------
__global__ void fc_softmax_kernel(const float* __restrict__ fw,
                                  const float* __restrict__ fb,
                                  float* __restrict__ out, int n) {
    int warp = (blockIdx.x * blockDim.x + threadIdx.x) >> 5;
    int lane = threadIdx.x & 31;
    if (warp >= n) return;
    const float* hr = g_agg + (size_t)warp * NH;

    float acc[NC];
#pragma unroll
    for (int c = 0; c < NC; c++) acc[c] = 0.0f;
#pragma unroll
    for (int kk = 0; kk < 4; kk++) {
        int k = lane + kk * 32;
        float hv = fmaxf(hr[k], 0.0f);
#pragma unroll
        for (int c = 0; c < NC; c++) acc[c] = fmaf(hv, __ldg(fw + k * NC + c), acc[c]);
    }
#pragma unroll
    for (int c = 0; c < NC; c++) {
#pragma unroll
        for (int off = 16; off; off >>= 1)
            acc[c] += __shfl_xor_sync(0xffffffffu, acc[c], off);
        acc[c] += fb[c];
    }
    float mx = acc[0];
#pragma unroll
    for (int c = 1; c < NC; c++) mx = fmaxf(mx, acc[c]);
    float ex[NC];
    float sum = 0.0f;
#pragma unroll
    for (int c = 0; c < NC; c++) { ex[c] = __expf(acc[c] - mx); sum += ex[c]; }
    float inv = 1.0f / sum;
    if (lane < NC) out[(size_t)warp * NC + lane] = ex[lane] * inv;
}

// ---------------- launch -------------------------------------------------
extern "C" void kernel_launch(void* const* d_in, const int* in_sizes, int n_in,
                              void* d_out, int out_size) {
    const float* x  = (const float*)d_in[0];
    const int*   ei = (const int*)d_in[1];
    const float* ew = (const float*)d_in[2];
    const float* W1 = (const float*)d_in[3];
    const float* b1 = (const float*)d_in[4];
    const float* W2 = (const float*)d_in[5];
    const float* b2 = (const float*)d_in[6];
    const float* W3 = (const float*)d_in[7];
    const float* b3 = (const float*)d_in[8];
    const float* fw = (const float*)d_in[9];
    const float* fb = (const float*)d_in[10];
    float* out = (float*)d_out;

    int N = in_sizes[0] / NF;
    int E = in_sizes[2];
    const int* src = ei;
    const int* dst = ei + E;

    __half* hbuf;
    float* aggbuf;
    uint32_t *whp, *wlp;
    cudaGetSymbolAddress((void**)&hbuf, g_h);
    cudaGetSymbolAddress((void**)&aggbuf, g_agg);
    cudaGetSymbolAddress((void**)&whp, g_whp);
    cudaGetSymbolAddress((void**)&wlp, g_wlp);

    const int T = 256;
    int gN = (N + T - 1) / T;
    int gE = (E + T - 1) / T;
    int gGa = (N * 32 + T - 1) / T;
    int gG = (N + 127) / 128;
    int nb = (N + SCANB - 1) / SCANB;

    prep_w<<<128, 256>>>(W1, W2, W3);
    init_deg_kernel<<<gN, T>>>(N);
    accum_deg_kernel<<<gE, T>>>(dst, ew, E);
    scan_phase1<<<nb, SCANB>>>(N);
    scan_phase23<<<gN, T>>>(nb, N);
    fill_kernel<<<gE, T>>>(src, dst, ew, E);

    tc_gemm<<<gG, T>>>(x, whp, wlp, hbuf, N, NF, 0);
    gather_kernel<<<gGa, T>>>(b1, N);
    tc_gemm<<<gG, T>>>(aggbuf, whp + 16384, wlp + 16384, hbuf, N, NH, 1);
    gather_kernel<<<gGa, T>>>(b2, N);
    tc_gemm<<<gG, T>>>(aggbuf, whp + 24576, wlp + 24576, hbuf, N, NH, 1);
    gather_kernel<<<gGa, T>>>(b3, N);
    fc_softmax_kernel<<<gGa, T>>>(fw, fb, out, N);
}

// round 17
// speedup vs baseline: 1.2467x; 1.0937x over previous
#include <cuda_runtime.h>
#include <cuda_fp16.h>
#include <math.h>
#include <stdint.h>

#define NF 256
#define NH 128
#define NC 10
#define NMAX 50000
#define EMAX 800000
#define SCANB 1024
#define KC 16
#define AST 24

// Scratch
__device__ __align__(16) __half g_h[(size_t)NMAX * NH];   // fp16 GEMM output
__device__ float g_agg[(size_t)NMAX * NH];
__device__ float g_deg[NMAX];
__device__ float g_dinv[NMAX];
__device__ float g_selfc[NMAX];
__device__ int   g_cnt[NMAX];
__device__ int   g_pos[NMAX];
__device__ int   g_rowoff[NMAX + 1];
__device__ int   g_csr_src[EMAX];
__device__ float g_csr_coef[EMAX];
__device__ int   g_bsum[(NMAX + SCANB - 1) / SCANB];
// pre-converted W, k2-major packed fp16x2 (lo=W[2k2][n], hi=W[2k2+1][n]):
// W1 @0 (128 k2 x 128 n), W2 @16384 (64x128), W3 @24576 (64x128)
__device__ __align__(16) uint32_t g_wp[32768];

// ---------------- helpers ------------------------------------------------
__device__ __forceinline__ uint32_t smem_u32(const void* p) {
    uint32_t a;
    asm("{ .reg .u64 t; cvta.to.shared.u64 t, %1; cvt.u32.u64 %0, t; }"
        : "=r"(a) : "l"(p));
    return a;
}
__device__ __forceinline__ uint32_t pack_h2(float a, float b) {
    __half2 p = __floats2half2_rn(a, b);
    return *reinterpret_cast<uint32_t*>(&p);
}

__device__ __forceinline__ void ldm4(uint32_t* r, uint32_t addr) {
    asm volatile("ldmatrix.sync.aligned.m8n8.x4.shared.b16 {%0,%1,%2,%3}, [%4];"
                 : "=r"(r[0]), "=r"(r[1]), "=r"(r[2]), "=r"(r[3]) : "r"(addr));
}
__device__ __forceinline__ void ldm2(uint32_t* r, uint32_t addr) {
    asm volatile("ldmatrix.sync.aligned.m8n8.x2.shared.b16 {%0,%1}, [%2];"
                 : "=r"(r[0]), "=r"(r[1]) : "r"(addr));
}
__device__ __forceinline__ void mma_fp16(float* d, const uint32_t* a, const uint32_t* b) {
    asm volatile(
        "mma.sync.aligned.m16n8k16.row.col.f32.f16.f16.f32 "
        "{%0,%1,%2,%3}, {%4,%5,%6,%7}, {%8,%9}, {%0,%1,%2,%3};"
        : "+f"(d[0]), "+f"(d[1]), "+f"(d[2]), "+f"(d[3])
        : "r"(a[0]), "r"(a[1]), "r"(a[2]), "r"(a[3]), "r"(b[0]), "r"(b[1]));
}

// ---------------- W pre-conversion (k2-major packed fp16, coalesced) -----
__global__ void prep_w(const float* __restrict__ W1, const float* __restrict__ W2,
                       const float* __restrict__ W3) {
    int idx = blockIdx.x * blockDim.x + threadIdx.x;   // 0..32767
    const float* W;
    int k2, n;
    if (idx < 16384) {
        W = W1;
        k2 = idx >> 7; n = idx & 127;
    } else if (idx < 24576) {
        int i2 = idx - 16384;
        W = W2;
        k2 = i2 >> 7; n = i2 & 127;
    } else {
        int i2 = idx - 24576;
        W = W3;
        k2 = i2 >> 7; n = i2 & 127;
    }
    float v0 = W[(size_t)(2 * k2) * 128 + n];
    float v1 = W[(size_t)(2 * k2 + 1) * 128 + n];
    g_wp[idx] = pack_h2(v0, v1);
}

// ======================= tensor-core GEMM (mma.sync fp16 single-pass) ====
// Cm[N x 128] (fp16) = A[N x K] (fp32) @ W (pre-converted fp16, k2-major)
// KC=16, 128-row tiles, 256 threads, 2 CTAs/SM.
__global__ __launch_bounds__(256, 2) void tc_gemm(const float* __restrict__ A,
                                                  const uint32_t* __restrict__ Wp,
                                                  __half* __restrict__ Cm,
                                                  int N, int K, int reluA) {
    __shared__ __align__(16) uint16_t Ah[128 * AST];
    __shared__ __align__(16) uint16_t Bh[128 * AST];

    int tid = threadIdx.x;
    int lane = tid & 31;
    int wid = tid >> 5;
    int wm = wid & 1;
    int wn = wid >> 1;
    int row0 = blockIdx.x * 128;

    float acc[4][4][4];
#pragma unroll
    for (int i = 0; i < 4; i++)
#pragma unroll
        for (int j = 0; j < 4; j++)
#pragma unroll
            for (int q = 0; q < 4; q++) acc[i][j][q] = 0.f;

    uint32_t aBase = smem_u32(Ah);
    uint32_t bBase = smem_u32(Bh);

    int aLRow = lane & 15;
    int aLK = (lane >> 4) * 8;
    int bLRow = lane & 7;
    int bLK = ((lane >> 3) & 1) * 8;

    for (int kb = 0; kb < K; kb += KC) {
        // ---- fill A: 128 rows x 16 k (fp32 -> fp16) ----
#pragma unroll
        for (int it = 0; it < 2; it++) {
            int idx = tid + it * 256;      // 0..511
            int row = idx >> 2;
            int f4 = idx & 3;
            float4 v = make_float4(0.f, 0.f, 0.f, 0.f);
            int gr = row0 + row;
            if (gr < N)
                v = *reinterpret_cast<const float4*>(A + (size_t)gr * K + kb + f4 * 4);
            if (reluA) {
                v.x = fmaxf(v.x, 0.f); v.y = fmaxf(v.y, 0.f);
                v.z = fmaxf(v.z, 0.f); v.w = fmaxf(v.w, 0.f);
            }
            uint32_t h01 = pack_h2(v.x, v.y);
            uint32_t h23 = pack_h2(v.z, v.w);
            int o = row * AST + f4 * 4;
            *reinterpret_cast<uint2*>(Ah + o) = make_uint2(h01, h23);
        }
        // ---- fill B: coalesced packed copy (8 k2 x 128 n per chunk) ----
        {
            int kb2 = kb >> 1;
#pragma unroll
            for (int it = 0; it < 4; it++) {
                int idx = tid + it * 256;  // 0..1023
                int k2 = idx >> 7;         // 0..7
                int n = idx & 127;
                uint32_t h = __ldg(Wp + (size_t)(kb2 + k2) * 128 + n);
                *reinterpret_cast<uint32_t*>(Bh + n * AST + k2 * 2) = h;
            }
        }
        __syncthreads();

        // ---- mma: single k16 step, single pass ----
        {
            uint32_t af[4][4];
#pragma unroll
            for (int mt = 0; mt < 4; mt++) {
                uint32_t off = (uint32_t)(((wm * 64 + mt * 16 + aLRow) * AST +
                                           aLK) * 2);
                ldm4(af[mt], aBase + off);
            }
            uint32_t bf[4][2];
#pragma unroll
            for (int nt = 0; nt < 4; nt++) {
                uint32_t off = (uint32_t)(((wn * 32 + nt * 8 + bLRow) * AST +
                                           bLK) * 2);
                ldm2(bf[nt], bBase + off);
            }
#pragma unroll
            for (int mt = 0; mt < 4; mt++)
#pragma unroll
                for (int nt = 0; nt < 4; nt++)
                    mma_fp16(acc[mt][nt], af[mt], bf[nt]);
        }
        __syncthreads();
    }

    int gid = lane >> 2;
    int tig = lane & 3;
#pragma unroll
    for (int mt = 0; mt < 4; mt++) {
        int r0 = row0 + wm * 64 + mt * 16 + gid;
        int r1 = r0 + 8;
#pragma unroll
        for (int nt = 0; nt < 4; nt++) {
            int col = wn * 32 + nt * 8 + tig * 2;
            if (r0 < N) {
                __half2 p = __floats2half2_rn(acc[mt][nt][0], acc[mt][nt][1]);
                *reinterpret_cast<__half2*>(Cm + (size_t)r0 * 128 + col) = p;
            }
            if (r1 < N) {
                __half2 p = __floats2half2_rn(acc[mt][nt][2], acc[mt][nt][3]);
                *reinterpret_cast<__half2*>(Cm + (size_t)r1 * 128 + col) = p;
            }
        }
    }
}

// ---------------- precompute ---------------------------------------------
__global__ void init_deg_kernel(int n) {
    int i = blockIdx.x * blockDim.x + threadIdx.x;
    if (i < n) { g_deg[i] = 1.0f; g_cnt[i] = 0; }
}

__global__ void accum_deg_kernel(const int* __restrict__ dst,
                                 const float* __restrict__ ew, int E) {
    int e = blockIdx.x * blockDim.x + threadIdx.x;
    if (e < E) {
        int d = dst[e];
        atomicAdd(&g_deg[d], ew[e]);
        atomicAdd(&g_cnt[d], 1);
    }
}

// scan phase1 with dinv fused
__global__ __launch_bounds__(SCANB) void scan_phase1(int n) {
    __shared__ int warpsum[32];
    int tid = threadIdx.x, lane = tid & 31, wid = tid >> 5;
    int i = blockIdx.x * SCANB + tid;

    if (i < n) {
        float d = g_deg[i];
        float r = (d > 0.0f) ? rsqrtf(d) : 0.0f;
        g_dinv[i] = r;
        g_selfc[i] = r * r;
    }

    int v = (i < n) ? g_cnt[i] : 0;
    int x = v;
#pragma unroll
    for (int off = 1; off < 32; off <<= 1) {
        int y = __shfl_up_sync(0xffffffffu, x, off);
        if (lane >= off) x += y;
    }
    if (lane == 31) warpsum[wid] = x;
    __syncthreads();
    if (wid == 0) {
        int s = warpsum[lane];
#pragma unroll
        for (int off = 1; off < 32; off <<= 1) {
            int y = __shfl_up_sync(0xffffffffu, s, off);
            if (lane >= off) s += y;
        }
        warpsum[lane] = s;
    }
    __syncthreads();
    int woff = wid ? warpsum[wid - 1] : 0;
    if (i < n) g_rowoff[i] = x + woff - v;
    if (tid == SCANB - 1) g_bsum[blockIdx.x] = x + woff;
}

// scan phase2+3 merged
__global__ void scan_phase23(int nb, int n) {
    __shared__ int boff_s[64];
    __shared__ int ws2[2];
    int tid = threadIdx.x;
    int lane = tid & 31;
    int w = tid >> 5;

    int v = 0, x = 0;
    if (tid < 64) {
        v = (tid < nb) ? g_bsum[tid] : 0;
        x = v;
#pragma unroll
        for (int off = 1; off < 32; off <<= 1) {
            int y = __shfl_up_sync(0xffffffffu, x, off);
            if (lane >= off) x += y;
        }
        if (lane == 31) ws2[w] = x;
    }
    __syncthreads();
    if (tid < 64) {
        int add = (w == 1) ? ws2[0] : 0;
        boff_s[tid] = x + add - v;
        if (blockIdx.x == 0 && tid == nb - 1) g_rowoff[n] = x + add;
    }
    __syncthreads();

    int i = blockIdx.x * blockDim.x + tid;
    if (i < n) {
        int r = g_rowoff[i] + boff_s[i / SCANB];
        g_rowoff[i] = r;
        g_pos[i] = r;
    }
}

__global__ void fill_kernel(const int* __restrict__ src, const int* __restrict__ dst,
                            const float* __restrict__ ew, int E) {
    int e = blockIdx.x * blockDim.x + threadIdx.x;
    if (e < E) {
        int s = src[e], d = dst[e];
        int slot = atomicAdd(&g_pos[d], 1);
        g_csr_src[slot] = s;
        g_csr_coef[slot] = g_dinv[s] * ew[e] * g_dinv[d];
    }
}

// ---------------- CSR gather aggregation (warp per node, fp16 h) ---------
__global__ void gather_kernel(const float* __restrict__ b, int n) {
    int t = blockIdx.x * blockDim.x + threadIdx.x;
    int node = t >> 5;
    int lane = t & 31;
    if (node >= n) return;

    const __half2* h2 = reinterpret_cast<const __half2*>(g_h);
    float4 bv = reinterpret_cast<const float4*>(b)[lane];
    float sc = g_selfc[node];

    float4 acc;
    {
        __half2 a0 = h2[(size_t)node * 64 + 2 * lane];
        __half2 a1 = h2[(size_t)node * 64 + 2 * lane + 1];
        float2 f0 = __half22float2(a0);
        float2 f1 = __half22float2(a1);
        acc.x = fmaf(f0.x, sc, bv.x);
        acc.y = fmaf(f0.y, sc, bv.y);
        acc.z = fmaf(f1.x, sc, bv.z);
        acc.w = fmaf(f1.y, sc, bv.w);
    }

    int beg = g_rowoff[node];
    int end = g_rowoff[node + 1];
    int e = beg;
    for (; e + 3 < end; e += 4) {
        int s0 = __ldg(g_csr_src + e);
        int s1 = __ldg(g_csr_src + e + 1);
        int s2 = __ldg(g_csr_src + e + 2);
        int s3 = __ldg(g_csr_src + e + 3);
        float w0 = __ldg(g_csr_coef + e);
        float w1 = __ldg(g_csr_coef + e + 1);
        float w2 = __ldg(g_csr_coef + e + 2);
        float w3 = __ldg(g_csr_coef + e + 3);
        __half2 a0 = h2[(size_t)s0 * 64 + 2 * lane];
        __half2 a1 = h2[(size_t)s0 * 64 + 2 * lane + 1];
        __half2 c0 = h2[(size_t)s1 * 64 + 2 * lane];
        __half2 c1 = h2[(size_t)s1 * 64 + 2 * lane + 1];
        __half2 d0 = h2[(size_t)s2 * 64 + 2 * lane];
        __half2 d1 = h2[(size_t)s2 * 64 + 2 * lane + 1];
        __half2 e0 = h2[(size_t)s3 * 64 + 2 * lane];
        __half2 e1 = h2[(size_t)s3 * 64 + 2 * lane + 1];
        float2 f0 = __half22float2(a0);
        float2 f1 = __half22float2(a1);
        float2 g0 = __half22float2(c0);
        float2 g1 = __half22float2(c1);
        float2 h0 = __half22float2(d0);
        float2 h1 = __half22float2(d1);
        float2 i0 = __half22float2(e0);
        float2 i1 = __half22float2(e1);
        acc.x = fmaf(f0.x, w0, acc.x);
        acc.y = fmaf(f0.y, w0, acc.y);
        acc.z = fmaf(f1.x, w0, acc.z);
        acc.w = fmaf(f1.y, w0, acc.w);
        acc.x = fmaf(g0.x, w1, acc.x);
        acc.y = fmaf(g0.y, w1, acc.y);
        acc.z = fmaf(g1.x, w1, acc.z);
        acc.w = fmaf(g1.y, w1, acc.w);
        acc.x = fmaf(h0.x, w2, acc.x);
        acc.y = fmaf(h0.y, w2, acc.y);
        acc.z = fmaf(h1.x, w2, acc.z);
        acc.w = fmaf(h1.y, w2, acc.w);
        acc.x = fmaf(i0.x, w3, acc.x);
        acc.y = fmaf(i0.y, w3, acc.y);
        acc.z = fmaf(i1.x, w3, acc.z);
        acc.w = fmaf(i1.y, w3, acc.w);
    }
    for (; e < end; e++) {
        int s0 = __ldg(g_csr_src + e);
        float w0 = __ldg(g_csr_coef + e);
        __half2 a0 = h2[(size_t)s0 * 64 + 2 * lane];
        __half2 a1 = h2[(size_t)s0 * 64 + 2 * lane + 1];
        float2 f0 = __half22float2(a0);
        float2 f1 = __half22float2(a1);
        acc.x = fmaf(f0.x, w0, acc.x);
        acc.y = fmaf(f0.y, w0, acc.y);
        acc.z = fmaf(f1.x, w0, acc.z);
        acc.w = fmaf(f1.y, w0, acc.w);
    }
    reinterpret_cast<float4*>(g_agg)[(size_t)node * 32 + lane] = acc;
}

// ---------------- FC + softmax (warp per node) ---------------------------
__global__ void fc_softmax_kernel(const float* __restrict__ fw,
                                  const float* __restrict__ fb,
                                  float* __restrict__ out, int n) {
    int warp = (blockIdx.x * blockDim.x + threadIdx.x) >> 5;
    int lane = threadIdx.x & 31;
    if (warp >= n) return;
    const float* hr = g_agg + (size_t)warp * NH;

    float acc[NC];
#pragma unroll
    for (int c = 0; c < NC; c++) acc[c] = 0.0f;
#pragma unroll
    for (int kk = 0; kk < 4; kk++) {
        int k = lane + kk * 32;
        float hv = fmaxf(hr[k], 0.0f);
#pragma unroll
        for (int c = 0; c < NC; c++) acc[c] = fmaf(hv, __ldg(fw + k * NC + c), acc[c]);
    }
#pragma unroll
    for (int c = 0; c < NC; c++) {
#pragma unroll
        for (int off = 16; off; off >>= 1)
            acc[c] += __shfl_xor_sync(0xffffffffu, acc[c], off);
        acc[c] += fb[c];
    }
    float mx = acc[0];
#pragma unroll
    for (int c = 1; c < NC; c++) mx = fmaxf(mx, acc[c]);
    float ex[NC];
    float sum = 0.0f;
#pragma unroll
    for (int c = 0; c < NC; c++) { ex[c] = __expf(acc[c] - mx); sum += ex[c]; }
    float inv = 1.0f / sum;
    if (lane < NC) out[(size_t)warp * NC + lane] = ex[lane] * inv;
}

// ---------------- launch -------------------------------------------------
extern "C" void kernel_launch(void* const* d_in, const int* in_sizes, int n_in,
                              void* d_out, int out_size) {
    const float* x  = (const float*)d_in[0];
    const int*   ei = (const int*)d_in[1];
    const float* ew = (const float*)d_in[2];
    const float* W1 = (const float*)d_in[3];
    const float* b1 = (const float*)d_in[4];
    const float* W2 = (const float*)d_in[5];
    const float* b2 = (const float*)d_in[6];
    const float* W3 = (const float*)d_in[7];
    const float* b3 = (const float*)d_in[8];
    const float* fw = (const float*)d_in[9];
    const float* fb = (const float*)d_in[10];
    float* out = (float*)d_out;

    int N = in_sizes[0] / NF;
    int E = in_sizes[2];
    const int* src = ei;
    const int* dst = ei + E;

    __half* hbuf;
    float* aggbuf;
    uint32_t* wp;
    cudaGetSymbolAddress((void**)&hbuf, g_h);
    cudaGetSymbolAddress((void**)&aggbuf, g_agg);
    cudaGetSymbolAddress((void**)&wp, g_wp);

    const int T = 256;
    int gN = (N + T - 1) / T;
    int gE = (E + T - 1) / T;
    int gGa = (N * 32 + T - 1) / T;
    int gG = (N + 127) / 128;
    int nb = (N + SCANB - 1) / SCANB;

    prep_w<<<128, 256>>>(W1, W2, W3);
    init_deg_kernel<<<gN, T>>>(N);
    accum_deg_kernel<<<gE, T>>>(dst, ew, E);
    scan_phase1<<<nb, SCANB>>>(N);
    scan_phase23<<<gN, T>>>(nb, N);
    fill_kernel<<<gE, T>>>(src, dst, ew, E);

    tc_gemm<<<gG, T>>>(x, wp, hbuf, N, NF, 0);
    gather_kernel<<<gGa, T>>>(b1, N);
    tc_gemm<<<gG, T>>>(aggbuf, wp + 16384, hbuf, N, NH, 1);
    gather_kernel<<<gGa, T>>>(b2, N);
    tc_gemm<<<gG, T>>>(aggbuf, wp + 24576, hbuf, N, NH, 1);
    gather_kernel<<<gGa, T>>>(b3, N);
    fc_softmax_kernel<<<gGa, T>>>(fw, fb, out, N);
}